// round 6
// baseline (speedup 1.0000x reference)
#include <cuda_runtime.h>
#include <cstdint>

// Shapes (fixed)
#define N_TOTAL 2048
#define T_DIM   128
#define F_DIM   32
#define K_DIM   32

#define NB      16                 // n per block
#define TC      8                  // t per chunk
#define CHUNKS  (T_DIM / TC)       // 16
#define THREADS 512                // 16 warps: 4 n-groups x 4 k-groups
#define NBLOCKS (N_TOTAL / NB)     // 128

#define XBUF_FLOATS (NB * TC * F_DIM)      // 4096 (16KB/slot)
#define CBUF_FLOATS (K_DIM * TC * F_DIM)   // 8192 (32KB/slot)
#define SMEM_BYTES  ((2 * XBUF_FLOATS + 2 * CBUF_FLOATS) * 4)  // 96KB
#define XBYTES      (XBUF_FLOATS * 4)
#define CBYTES      (CBUF_FLOATS * 4)

typedef unsigned long long u64;

__device__ __forceinline__ void cp_async16(uint32_t dst, const void* src) {
    asm volatile("cp.async.cg.shared.global [%0], [%1], 16;\n" :: "r"(dst), "l"(src));
}
__device__ __forceinline__ void cp_commit() {
    asm volatile("cp.async.commit_group;\n" ::: "memory");
}
__device__ __forceinline__ void cp_wait1() {
    asm volatile("cp.async.wait_group 1;\n" ::: "memory");
}
__device__ __forceinline__ void ffma2(u64& d, u64 a, u64 b, u64 c) {
    asm("fma.rn.f32x2 %0, %1, %2, %3;" : "=l"(d) : "l"(a), "l"(b), "l"(c));
}
__device__ __forceinline__ u64 fadd2(u64 a, u64 b) {
    u64 d; asm("add.rn.f32x2 %0, %1, %2;" : "=l"(d) : "l"(a), "l"(b)); return d;
}
__device__ __forceinline__ float fsqrt_approx(float v) {
    float r; asm("sqrt.approx.f32 %0, %1;" : "=f"(r) : "f"(v)); return r;
}
__device__ __forceinline__ float frcp_approx(float v) {
    float r; asm("rcp.approx.f32 %0, %1;" : "=f"(r) : "f"(v)); return r;
}
__device__ __forceinline__ u64 lds64(const float* p) {
    return *reinterpret_cast<const u64*>(p);
}
__device__ __forceinline__ float lo32(u64 v) { return __uint_as_float((unsigned)v); }
__device__ __forceinline__ float hi32(u64 v) { return __uint_as_float((unsigned)(v >> 32)); }

#define NEG2_PACKED 0xC0000000C0000000ULL

extern "C" __global__ void __launch_bounds__(THREADS, 1)
ts_clustering_kernel(const float* __restrict__ x,
                     const float* __restrict__ clusters,
                     float* __restrict__ out) {
    extern __shared__ float smem[];
    const uint32_t smem_u32 = (uint32_t)__cvta_generic_to_shared(smem);

    const int tid  = threadIdx.x;
    const int lane = tid & 31;
    const int w    = tid >> 5;          // 0..15
    const int wn   = w & 3;             // n-group: 4 n each
    const int wk   = w >> 2;            // k-group: 8 k each
    const int fp   = lane & 15;         // f-pair 0..15
    const int nsub = lane >> 4;         // n-half
    const int nBase = blockIdx.x * NB;

    const int base_n = wn * 4 + nsub * 2;   // 2 n's per lane
    const int base_k = wk * 8;              // 8 k's per warp

    // ---- persistent prefetch pointers (advance 1KB per chunk) ----------------
    // x chunk: 1024 x 16B -> 2 per thread;  c chunk: 2048 x 16B -> 4 per thread
    const char* xsrc[2];
    uint32_t    xdst[2];
    #pragma unroll
    for (int r = 0; r < 2; r++) {
        int idx = tid + r * THREADS;
        int n   = idx >> 6;
        int rem = idx & 63;
        xsrc[r] = (const char*)x + ((size_t)(nBase + n) * T_DIM) * (F_DIM * 4)
                + (size_t)rem * 16;
        xdst[r] = smem_u32 + (uint32_t)idx * 16;
    }
    const char* csrc[4];
    uint32_t    cdst[4];
    #pragma unroll
    for (int r = 0; r < 4; r++) {
        int idx = tid + r * THREADS;
        int k   = idx >> 6;
        int rem = idx & 63;
        csrc[r] = (const char*)clusters + ((size_t)k * T_DIM) * (F_DIM * 4)
                + (size_t)rem * 16;
        cdst[r] = smem_u32 + (uint32_t)(2 * XBYTES) + (uint32_t)idx * 16;
    }

    auto prefetch = [&](int buf) {
        const uint32_t xo = (uint32_t)buf * XBYTES;
        const uint32_t co = (uint32_t)buf * CBYTES;
        #pragma unroll
        for (int r = 0; r < 2; r++) { cp_async16(xdst[r] + xo, xsrc[r]); xsrc[r] += TC * F_DIM * 4; }
        #pragma unroll
        for (int r = 0; r < 4; r++) { cp_async16(cdst[r] + co, csrc[r]); csrc[r] += TC * F_DIM * 4; }
    };

    // ---- accumulators --------------------------------------------------------
    u64 acc[2][8];
    #pragma unroll
    for (int i = 0; i < 2; i++)
        #pragma unroll
        for (int j = 0; j < 8; j++) acc[i][j] = 0ULL;
    u64 sx2p[2] = {0ULL, 0ULL};               // x^2 partials, t-phase (t&3)==wk
    u64 sc2p[4] = {0ULL, 0ULL, 0ULL, 0ULL};   // c^2 partials (nsub k-quarter), (t&3)==wn

    prefetch(0);
    cp_commit();

    for (int ci = 0; ci < CHUNKS; ci++) {
        if (ci + 1 < CHUNKS) prefetch((ci + 1) & 1);
        cp_commit();            // uniform group count (empty last group)
        cp_wait1();
        __syncthreads();

        const float* xs = smem + (ci & 1) * XBUF_FLOATS;                    // [NB][TC][F]
        const float* cs = smem + 2 * XBUF_FLOATS + (ci & 1) * CBUF_FLOATS;  // [K][TC][F]
        const float* xp = xs + (base_n * TC) * F_DIM + 2 * fp;
        const float* cp = cs + (base_k * TC) * F_DIM + 2 * fp;

        #pragma unroll
        for (int t = 0; t < TC; t++) {
            u64 xr[2], cr[8];
            #pragma unroll
            for (int i = 0; i < 2; i++)
                xr[i] = lds64(xp + (i * TC + t) * F_DIM);
            #pragma unroll
            for (int j = 0; j < 8; j++)
                cr[j] = lds64(cp + (j * TC + t) * F_DIM);
            #pragma unroll
            for (int i = 0; i < 2; i++)
                #pragma unroll
                for (int j = 0; j < 8; j++)
                    ffma2(acc[i][j], xr[i], cr[j], acc[i][j]);
            if ((t & 3) == wk) {
                #pragma unroll
                for (int i = 0; i < 2; i++) ffma2(sx2p[i], xr[i], xr[i], sx2p[i]);
            }
            if ((t & 3) == wn) {                 // lane owns k-quarter [base_k+4*nsub, +4)
                #pragma unroll
                for (int j = 0; j < 4; j++)
                    ffma2(sc2p[j], cr[nsub * 4 + j], cr[nsub * 4 + j], sc2p[j]);
            }
        }
        __syncthreads();
    }

    // ---- epilogue ------------------------------------------------------------
    // smem reuse: x2part [4 wk][16 n][16 fp] pairs = 2048 floats
    //             c2part [4 wn][32 k][16 fp] pairs = 4096 floats @ +2048
    //             dsts   [16 n][32 k]               =  512 floats @ +6144
    __syncthreads();
    float* x2part = smem;
    float* c2part = smem + 2048;
    float* dsts   = smem + 6144;

    #pragma unroll
    for (int i = 0; i < 2; i++) {
        int n = base_n + i;
        *reinterpret_cast<u64*>(&x2part[2 * ((wk * 16 + n) * 16 + fp)]) = sx2p[i];
    }
    #pragma unroll
    for (int j = 0; j < 4; j++) {
        int k = base_k + nsub * 4 + j;
        *reinterpret_cast<u64*>(&c2part[2 * ((wn * 32 + k) * 16 + fp)]) = sc2p[j];
    }
    __syncthreads();

    // c2 totals for this warp's 8 k's at this fp
    u64 c2p[8];
    #pragma unroll
    for (int j = 0; j < 8; j++) {
        int k = base_k + j;
        u64 s0 = fadd2(lds64(&c2part[2 * ((0 * 32 + k) * 16 + fp)]),
                       lds64(&c2part[2 * ((1 * 32 + k) * 16 + fp)]));
        u64 s1 = fadd2(lds64(&c2part[2 * ((2 * 32 + k) * 16 + fp)]),
                       lds64(&c2part[2 * ((3 * 32 + k) * 16 + fp)]));
        c2p[j] = fadd2(s0, s1);
    }

    #pragma unroll
    for (int i = 0; i < 2; i++) {
        int n = base_n + i;
        u64 x2p = fadd2(fadd2(lds64(&x2part[2 * ((0 * 16 + n) * 16 + fp)]),
                              lds64(&x2part[2 * ((1 * 16 + n) * 16 + fp)])),
                        fadd2(lds64(&x2part[2 * ((2 * 16 + n) * 16 + fp)]),
                              lds64(&x2part[2 * ((3 * 16 + n) * 16 + fp)])));
        #pragma unroll
        for (int j = 0; j < 8; j++) {
            u64 s  = fadd2(x2p, c2p[j]);
            u64 sq;
            ffma2(sq, acc[i][j], NEG2_PACKED, s);   // x2 + c2 - 2*xc (both f's)
            float ed = fsqrt_approx(fmaxf(lo32(sq), 0.0f))
                     + fsqrt_approx(fmaxf(hi32(sq), 0.0f));
            #pragma unroll
            for (int off = 8; off > 0; off >>= 1)    // reduce 16 f-pairs (stays in half)
                ed += __shfl_xor_sync(0xffffffffu, ed, off);
            if (fp == 0)                              // lanes 0 & 16: distinct n
                dsts[n * K_DIM + (base_k + j)] = ed;
        }
    }
    __syncthreads();

    // ---- Student-t + per-n normalization: warp w handles n = w ---------------
    {
        float d = dsts[w * K_DIM + lane];
        float q = frcp_approx(fmaf(d, d, 1.0f));     // alpha = 1
        float sum = q;
        #pragma unroll
        for (int off = 16; off > 0; off >>= 1)
            sum += __shfl_xor_sync(0xffffffffu, sum, off);
        out[(size_t)(nBase + w) * K_DIM + lane] = q * frcp_approx(sum);
    }
}

extern "C" void kernel_launch(void* const* d_in, const int* in_sizes, int n_in,
                              void* d_out, int out_size) {
    const float* x        = (const float*)d_in[0];   // (2048, 128, 32)
    const float* clusters = (const float*)d_in[1];   // (32, 128, 32)
    float* out            = (float*)d_out;           // (2048, 32)
    (void)in_sizes; (void)n_in; (void)out_size;

    cudaFuncSetAttribute(ts_clustering_kernel,
                         cudaFuncAttributeMaxDynamicSharedMemorySize, SMEM_BYTES);
    ts_clustering_kernel<<<NBLOCKS, THREADS, SMEM_BYTES>>>(x, clusters, out);
}

// round 7
// speedup vs baseline: 1.0370x; 1.0370x over previous
#include <cuda_runtime.h>
#include <cstdint>

// Shapes (fixed)
#define N_TOTAL 2048
#define T_DIM   128
#define F_DIM   32
#define K_DIM   32

#define NB      16                 // n per block
#define TC      8                  // t per chunk
#define CHUNKS  (T_DIM / TC)       // 16
#define THREADS 512                // 16 warps: 4 n-groups x 4 k-groups
#define NBLOCKS (N_TOTAL / NB)     // 128

#define XBUF_FLOATS (NB * TC * F_DIM)      // 4096 (16KB/slot)
#define CBUF_FLOATS (K_DIM * TC * F_DIM)   // 8192 (32KB/slot)
#define SMEM_BYTES  ((2 * XBUF_FLOATS + 2 * CBUF_FLOATS) * 4)  // 96KB
#define XBYTES      (XBUF_FLOATS * 4)
#define CBYTES      (CBUF_FLOATS * 4)

typedef unsigned long long u64;

__device__ __forceinline__ void cp_async16(uint32_t dst, const void* src) {
    asm volatile("cp.async.cg.shared.global [%0], [%1], 16;\n" :: "r"(dst), "l"(src));
}
__device__ __forceinline__ void cp_commit() {
    asm volatile("cp.async.commit_group;\n" ::: "memory");
}
__device__ __forceinline__ void cp_wait1() {
    asm volatile("cp.async.wait_group 1;\n" ::: "memory");
}
__device__ __forceinline__ void ffma2(u64& d, u64 a, u64 b, u64 c) {
    asm("fma.rn.f32x2 %0, %1, %2, %3;" : "=l"(d) : "l"(a), "l"(b), "l"(c));
}
__device__ __forceinline__ u64 fadd2(u64 a, u64 b) {
    u64 d; asm("add.rn.f32x2 %0, %1, %2;" : "=l"(d) : "l"(a), "l"(b)); return d;
}
__device__ __forceinline__ float fsqrt_approx(float v) {
    float r; asm("sqrt.approx.f32 %0, %1;" : "=f"(r) : "f"(v)); return r;
}
__device__ __forceinline__ float frcp_approx(float v) {
    float r; asm("rcp.approx.f32 %0, %1;" : "=f"(r) : "f"(v)); return r;
}
__device__ __forceinline__ u64 lds64(const float* p) {
    return *reinterpret_cast<const u64*>(p);
}
__device__ __forceinline__ float lo32(u64 v) { return __uint_as_float((unsigned)v); }
__device__ __forceinline__ float hi32(u64 v) { return __uint_as_float((unsigned)(v >> 32)); }

#define NEG2_PACKED 0xC0000000C0000000ULL

extern "C" __global__ void __launch_bounds__(THREADS, 1)
ts_clustering_kernel(const float* __restrict__ x,
                     const float* __restrict__ clusters,
                     float* __restrict__ out) {
    extern __shared__ float smem[];
    const uint32_t smem_u32 = (uint32_t)__cvta_generic_to_shared(smem);

    const int tid  = threadIdx.x;
    const int lane = tid & 31;
    const int w    = tid >> 5;          // 0..15
    const int wn   = w & 3;             // n-group: 4 n each
    const int wk   = w >> 2;            // k-group: 8 k each
    const int fp   = lane & 15;         // f-pair 0..15
    const int nsub = lane >> 4;         // n-half
    const int nBase = blockIdx.x * NB;

    const int base_n = wn * 4 + nsub * 2;   // 2 n's per lane
    const int base_k = wk * 8;              // 8 k's per warp

    // ---- persistent prefetch pointers (advance 1KB per chunk) ----------------
    // x chunk: 1024 x 16B -> 2 per thread;  c chunk: 2048 x 16B -> 4 per thread
    const char* xsrc[2];
    uint32_t    xdst[2];
    #pragma unroll
    for (int r = 0; r < 2; r++) {
        int idx = tid + r * THREADS;
        int n   = idx >> 6;
        int rem = idx & 63;
        xsrc[r] = (const char*)x + ((size_t)(nBase + n) * T_DIM) * (F_DIM * 4)
                + (size_t)rem * 16;
        xdst[r] = smem_u32 + (uint32_t)idx * 16;
    }
    const char* csrc[4];
    uint32_t    cdst[4];
    #pragma unroll
    for (int r = 0; r < 4; r++) {
        int idx = tid + r * THREADS;
        int k   = idx >> 6;
        int rem = idx & 63;
        csrc[r] = (const char*)clusters + ((size_t)k * T_DIM) * (F_DIM * 4)
                + (size_t)rem * 16;
        cdst[r] = smem_u32 + (uint32_t)(2 * XBYTES) + (uint32_t)idx * 16;
    }

    auto prefetch = [&](int buf) {
        const uint32_t xo = (uint32_t)buf * XBYTES;
        const uint32_t co = (uint32_t)buf * CBYTES;
        #pragma unroll
        for (int r = 0; r < 2; r++) { cp_async16(xdst[r] + xo, xsrc[r]); xsrc[r] += TC * F_DIM * 4; }
        #pragma unroll
        for (int r = 0; r < 4; r++) { cp_async16(cdst[r] + co, csrc[r]); csrc[r] += TC * F_DIM * 4; }
    };

    // ---- accumulators --------------------------------------------------------
    u64 acc[2][8];
    #pragma unroll
    for (int i = 0; i < 2; i++)
        #pragma unroll
        for (int j = 0; j < 8; j++) acc[i][j] = 0ULL;
    u64 sx2p[2] = {0ULL, 0ULL};               // x^2 partials, t-phase (t&3)==wk
    u64 sc2p[4] = {0ULL, 0ULL, 0ULL, 0ULL};   // c^2 partials (nsub k-quarter), (t&3)==wn

    prefetch(0);
    cp_commit();

    for (int ci = 0; ci < CHUNKS; ci++) {
        if (ci + 1 < CHUNKS) prefetch((ci + 1) & 1);
        cp_commit();            // uniform group count (empty last group)
        cp_wait1();
        __syncthreads();

        const float* xs = smem + (ci & 1) * XBUF_FLOATS;                    // [NB][TC][F]
        const float* cs = smem + 2 * XBUF_FLOATS + (ci & 1) * CBUF_FLOATS;  // [K][TC][F]
        const float* xp = xs + (base_n * TC) * F_DIM + 2 * fp;
        const float* cp = cs + (base_k * TC) * F_DIM + 2 * fp;

        #pragma unroll
        for (int t = 0; t < TC; t++) {
            u64 xr[2], cr[8];
            #pragma unroll
            for (int i = 0; i < 2; i++)
                xr[i] = lds64(xp + (i * TC + t) * F_DIM);
            #pragma unroll
            for (int j = 0; j < 8; j++)
                cr[j] = lds64(cp + (j * TC + t) * F_DIM);
            #pragma unroll
            for (int i = 0; i < 2; i++)
                #pragma unroll
                for (int j = 0; j < 8; j++)
                    ffma2(acc[i][j], xr[i], cr[j], acc[i][j]);
            if ((t & 3) == wk) {
                #pragma unroll
                for (int i = 0; i < 2; i++) ffma2(sx2p[i], xr[i], xr[i], sx2p[i]);
            }
            if ((t & 3) == wn) {                 // lane owns k-quarter [base_k+4*nsub, +4)
                #pragma unroll
                for (int j = 0; j < 4; j++)
                    ffma2(sc2p[j], cr[nsub * 4 + j], cr[nsub * 4 + j], sc2p[j]);
            }
        }
        __syncthreads();
    }

    // ---- epilogue ------------------------------------------------------------
    // smem reuse: x2part [4 wk][16 n][16 fp] pairs = 2048 floats
    //             c2part [4 wn][32 k][16 fp] pairs = 4096 floats @ +2048
    //             dsts   [16 n][32 k]               =  512 floats @ +6144
    __syncthreads();
    float* x2part = smem;
    float* c2part = smem + 2048;
    float* dsts   = smem + 6144;

    #pragma unroll
    for (int i = 0; i < 2; i++) {
        int n = base_n + i;
        *reinterpret_cast<u64*>(&x2part[2 * ((wk * 16 + n) * 16 + fp)]) = sx2p[i];
    }
    #pragma unroll
    for (int j = 0; j < 4; j++) {
        int k = base_k + nsub * 4 + j;
        *reinterpret_cast<u64*>(&c2part[2 * ((wn * 32 + k) * 16 + fp)]) = sc2p[j];
    }
    __syncthreads();

    // c2 totals for this warp's 8 k's at this fp
    u64 c2p[8];
    #pragma unroll
    for (int j = 0; j < 8; j++) {
        int k = base_k + j;
        u64 s0 = fadd2(lds64(&c2part[2 * ((0 * 32 + k) * 16 + fp)]),
                       lds64(&c2part[2 * ((1 * 32 + k) * 16 + fp)]));
        u64 s1 = fadd2(lds64(&c2part[2 * ((2 * 32 + k) * 16 + fp)]),
                       lds64(&c2part[2 * ((3 * 32 + k) * 16 + fp)]));
        c2p[j] = fadd2(s0, s1);
    }

    #pragma unroll
    for (int i = 0; i < 2; i++) {
        int n = base_n + i;
        u64 x2p = fadd2(fadd2(lds64(&x2part[2 * ((0 * 16 + n) * 16 + fp)]),
                              lds64(&x2part[2 * ((1 * 16 + n) * 16 + fp)])),
                        fadd2(lds64(&x2part[2 * ((2 * 16 + n) * 16 + fp)]),
                              lds64(&x2part[2 * ((3 * 16 + n) * 16 + fp)])));
        #pragma unroll
        for (int j = 0; j < 8; j++) {
            u64 s  = fadd2(x2p, c2p[j]);
            u64 sq;
            ffma2(sq, acc[i][j], NEG2_PACKED, s);   // x2 + c2 - 2*xc (both f's)
            float ed = fsqrt_approx(fmaxf(lo32(sq), 0.0f))
                     + fsqrt_approx(fmaxf(hi32(sq), 0.0f));
            #pragma unroll
            for (int off = 8; off > 0; off >>= 1)    // reduce 16 f-pairs (stays in half)
                ed += __shfl_xor_sync(0xffffffffu, ed, off);
            if (fp == 0)                              // lanes 0 & 16: distinct n
                dsts[n * K_DIM + (base_k + j)] = ed;
        }
    }
    __syncthreads();

    // ---- Student-t + per-n normalization: warp w handles n = w ---------------
    {
        float d = dsts[w * K_DIM + lane];
        float q = frcp_approx(fmaf(d, d, 1.0f));     // alpha = 1
        float sum = q;
        #pragma unroll
        for (int off = 16; off > 0; off >>= 1)
            sum += __shfl_xor_sync(0xffffffffu, sum, off);
        out[(size_t)(nBase + w) * K_DIM + lane] = q * frcp_approx(sum);
    }
}

extern "C" void kernel_launch(void* const* d_in, const int* in_sizes, int n_in,
                              void* d_out, int out_size) {
    const float* x        = (const float*)d_in[0];   // (2048, 128, 32)
    const float* clusters = (const float*)d_in[1];   // (32, 128, 32)
    float* out            = (float*)d_out;           // (2048, 32)
    (void)in_sizes; (void)n_in; (void)out_size;

    cudaFuncSetAttribute(ts_clustering_kernel,
                         cudaFuncAttributeMaxDynamicSharedMemorySize, SMEM_BYTES);
    ts_clustering_kernel<<<NBLOCKS, THREADS, SMEM_BYTES>>>(x, clusters, out);
}

// round 8
// speedup vs baseline: 2.7039x; 2.6074x over previous
#include <cuda_runtime.h>
#include <cstdint>

// Shapes (fixed)
#define N_TOTAL 2048
#define T_DIM   128
#define F_DIM   32
#define K_DIM   32

#define NB      16                 // n per block
#define TC      8                  // t per chunk
#define CHUNKS  (T_DIM / TC)       // 16
#define THREADS 512                // 16 warps: 4 n-groups x 4 k-groups
#define NBLOCKS (N_TOTAL / NB)     // 128

#define XBUF_FLOATS (NB * TC * F_DIM)      // 4096 (16KB/slot)
#define CBUF_FLOATS (K_DIM * TC * F_DIM)   // 8192 (32KB/slot)
#define SMEM_BYTES  ((2 * XBUF_FLOATS + 2 * CBUF_FLOATS) * 4)  // 96KB
#define XBYTES      (XBUF_FLOATS * 4)
#define CBYTES      (CBUF_FLOATS * 4)

typedef unsigned long long u64;

__device__ __forceinline__ void cp_async16(uint32_t dst, const void* src) {
    asm volatile("cp.async.cg.shared.global [%0], [%1], 16;\n" :: "r"(dst), "l"(src));
}
__device__ __forceinline__ void cp_commit() {
    asm volatile("cp.async.commit_group;\n" ::: "memory");
}
__device__ __forceinline__ void cp_wait1() {
    asm volatile("cp.async.wait_group 1;\n" ::: "memory");
}
__device__ __forceinline__ void ffma2(u64& d, u64 a, u64 b, u64 c) {
    asm("fma.rn.f32x2 %0, %1, %2, %3;" : "=l"(d) : "l"(a), "l"(b), "l"(c));
}
__device__ __forceinline__ u64 fadd2(u64 a, u64 b) {
    u64 d; asm("add.rn.f32x2 %0, %1, %2;" : "=l"(d) : "l"(a), "l"(b)); return d;
}
__device__ __forceinline__ float fsqrt_approx(float v) {
    float r; asm("sqrt.approx.f32 %0, %1;" : "=f"(r) : "f"(v)); return r;
}
__device__ __forceinline__ float frcp_approx(float v) {
    float r; asm("rcp.approx.f32 %0, %1;" : "=f"(r) : "f"(v)); return r;
}
__device__ __forceinline__ u64 lds64(const float* p) {
    return *reinterpret_cast<const u64*>(p);
}
__device__ __forceinline__ float lo32(u64 v) { return __uint_as_float((unsigned)v); }
__device__ __forceinline__ float hi32(u64 v) { return __uint_as_float((unsigned)(v >> 32)); }

#define NEG2_PACKED 0xC0000000C0000000ULL

extern "C" __global__ void __launch_bounds__(THREADS, 1)
ts_clustering_kernel(const float* __restrict__ x,
                     const float* __restrict__ clusters,
                     float* __restrict__ out) {
    extern __shared__ float smem[];
    const uint32_t smem_u32 = (uint32_t)__cvta_generic_to_shared(smem);

    const int tid  = threadIdx.x;
    const int lane = tid & 31;
    const int w    = tid >> 5;          // 0..15
    const int wn   = w & 3;             // n-group: 4 n each
    const int wk   = w >> 2;            // k-group: 8 k each
    const int fp   = lane & 15;         // f-pair 0..15
    const int nsub = lane >> 4;         // n-half
    const int nBase = blockIdx.x * NB;

    const int base_n = wn * 4 + nsub * 2;   // 2 n's per lane
    const int base_k = wk * 8;              // 8 k's per warp

    // ---- persistent prefetch pointers (static unrolled indexing only) --------
    const char* xsrc0; const char* xsrc1;
    uint32_t    xdst0, xdst1;
    {
        int idx0 = tid, idx1 = tid + THREADS;
        xsrc0 = (const char*)x + ((size_t)(nBase + (idx0 >> 6)) * T_DIM) * (F_DIM * 4)
              + (size_t)(idx0 & 63) * 16;
        xsrc1 = (const char*)x + ((size_t)(nBase + (idx1 >> 6)) * T_DIM) * (F_DIM * 4)
              + (size_t)(idx1 & 63) * 16;
        xdst0 = smem_u32 + (uint32_t)idx0 * 16;
        xdst1 = smem_u32 + (uint32_t)idx1 * 16;
    }
    const char* csrc0; const char* csrc1; const char* csrc2; const char* csrc3;
    uint32_t    cdst0, cdst1, cdst2, cdst3;
    {
        int i0 = tid, i1 = tid + THREADS, i2 = tid + 2 * THREADS, i3 = tid + 3 * THREADS;
        csrc0 = (const char*)clusters + ((size_t)(i0 >> 6) * T_DIM) * (F_DIM * 4) + (size_t)(i0 & 63) * 16;
        csrc1 = (const char*)clusters + ((size_t)(i1 >> 6) * T_DIM) * (F_DIM * 4) + (size_t)(i1 & 63) * 16;
        csrc2 = (const char*)clusters + ((size_t)(i2 >> 6) * T_DIM) * (F_DIM * 4) + (size_t)(i2 & 63) * 16;
        csrc3 = (const char*)clusters + ((size_t)(i3 >> 6) * T_DIM) * (F_DIM * 4) + (size_t)(i3 & 63) * 16;
        cdst0 = smem_u32 + (uint32_t)(2 * XBYTES) + (uint32_t)i0 * 16;
        cdst1 = smem_u32 + (uint32_t)(2 * XBYTES) + (uint32_t)i1 * 16;
        cdst2 = smem_u32 + (uint32_t)(2 * XBYTES) + (uint32_t)i2 * 16;
        cdst3 = smem_u32 + (uint32_t)(2 * XBYTES) + (uint32_t)i3 * 16;
    }
    const int STEP = TC * F_DIM * 4;   // 1KB per chunk advance

    auto prefetch = [&](int buf) {
        const uint32_t xo = (uint32_t)buf * XBYTES;
        const uint32_t co = (uint32_t)buf * CBYTES;
        cp_async16(xdst0 + xo, xsrc0); xsrc0 += STEP;
        cp_async16(xdst1 + xo, xsrc1); xsrc1 += STEP;
        cp_async16(cdst0 + co, csrc0); csrc0 += STEP;
        cp_async16(cdst1 + co, csrc1); csrc1 += STEP;
        cp_async16(cdst2 + co, csrc2); csrc2 += STEP;
        cp_async16(cdst3 + co, csrc3); csrc3 += STEP;
    };

    // ---- accumulators (ALL static indexing) ----------------------------------
    u64 acc[2][8];
    #pragma unroll
    for (int i = 0; i < 2; i++)
        #pragma unroll
        for (int j = 0; j < 8; j++) acc[i][j] = 0ULL;
    u64 sx2p[2] = {0ULL, 0ULL};                               // (t&3)==wk phase
    u64 sc2p[8] = {0ULL,0ULL,0ULL,0ULL,0ULL,0ULL,0ULL,0ULL}; // (t&3)==wn phase

    prefetch(0);
    cp_commit();

    for (int ci = 0; ci < CHUNKS; ci++) {
        if (ci + 1 < CHUNKS) prefetch((ci + 1) & 1);
        cp_commit();            // uniform group count
        cp_wait1();
        __syncthreads();

        const float* xs = smem + (ci & 1) * XBUF_FLOATS;                    // [NB][TC][F]
        const float* cs = smem + 2 * XBUF_FLOATS + (ci & 1) * CBUF_FLOATS;  // [K][TC][F]
        const float* xp = xs + (base_n * TC) * F_DIM + 2 * fp;
        const float* cp = cs + (base_k * TC) * F_DIM + 2 * fp;

        #pragma unroll
        for (int t = 0; t < TC; t++) {
            u64 xr[2], cr[8];
            #pragma unroll
            for (int i = 0; i < 2; i++)
                xr[i] = lds64(xp + (i * TC + t) * F_DIM);
            #pragma unroll
            for (int j = 0; j < 8; j++)
                cr[j] = lds64(cp + (j * TC + t) * F_DIM);
            #pragma unroll
            for (int i = 0; i < 2; i++)
                #pragma unroll
                for (int j = 0; j < 8; j++)
                    ffma2(acc[i][j], xr[i], cr[j], acc[i][j]);
            if ((t & 3) == wk) {          // static t, uniform wk
                ffma2(sx2p[0], xr[0], xr[0], sx2p[0]);
                ffma2(sx2p[1], xr[1], xr[1], sx2p[1]);
            }
            if ((t & 3) == wn) {          // static t, uniform wn — static indices
                #pragma unroll
                for (int j = 0; j < 8; j++)
                    ffma2(sc2p[j], cr[j], cr[j], sc2p[j]);
            }
        }
        __syncthreads();
    }

    // ---- epilogue ------------------------------------------------------------
    // smem reuse: x2part [4 wk][16 n][16 fp] pairs = 2048 floats
    //             c2part [4 wn][32 k][16 fp] pairs = 4096 floats @ +2048
    //             dsts   [16 n][32 k]              =  512 floats @ +6144
    __syncthreads();
    float* x2part = smem;
    float* c2part = smem + 2048;
    float* dsts   = smem + 6144;

    #pragma unroll
    for (int i = 0; i < 2; i++) {
        int n = base_n + i;
        *reinterpret_cast<u64*>(&x2part[2 * ((wk * 16 + n) * 16 + fp)]) = sx2p[i];
    }
    if (nsub == 0) {                       // both halves hold identical sc2p
        #pragma unroll
        for (int j = 0; j < 8; j++) {
            int k = base_k + j;
            *reinterpret_cast<u64*>(&c2part[2 * ((wn * 32 + k) * 16 + fp)]) = sc2p[j];
        }
    }
    __syncthreads();

    // c2 totals for this warp's 8 k's at this fp (sum 4 wn phases)
    u64 c2p[8];
    #pragma unroll
    for (int j = 0; j < 8; j++) {
        int k = base_k + j;
        u64 s0 = fadd2(lds64(&c2part[2 * ((0 * 32 + k) * 16 + fp)]),
                       lds64(&c2part[2 * ((1 * 32 + k) * 16 + fp)]));
        u64 s1 = fadd2(lds64(&c2part[2 * ((2 * 32 + k) * 16 + fp)]),
                       lds64(&c2part[2 * ((3 * 32 + k) * 16 + fp)]));
        c2p[j] = fadd2(s0, s1);
    }

    #pragma unroll
    for (int i = 0; i < 2; i++) {
        int n = base_n + i;
        u64 x2p = fadd2(fadd2(lds64(&x2part[2 * ((0 * 16 + n) * 16 + fp)]),
                              lds64(&x2part[2 * ((1 * 16 + n) * 16 + fp)])),
                        fadd2(lds64(&x2part[2 * ((2 * 16 + n) * 16 + fp)]),
                              lds64(&x2part[2 * ((3 * 16 + n) * 16 + fp)])));
        #pragma unroll
        for (int j = 0; j < 8; j++) {
            u64 s  = fadd2(x2p, c2p[j]);
            u64 sq;
            ffma2(sq, acc[i][j], NEG2_PACKED, s);   // x2 + c2 - 2*xc (both f's)
            float ed = fsqrt_approx(fmaxf(lo32(sq), 0.0f))
                     + fsqrt_approx(fmaxf(hi32(sq), 0.0f));
            #pragma unroll
            for (int off = 8; off > 0; off >>= 1)   // reduce 16 f-pairs per half
                ed += __shfl_xor_sync(0xffffffffu, ed, off);
            if (fp == 0)                             // lanes 0 & 16: distinct n
                dsts[n * K_DIM + (base_k + j)] = ed;
        }
    }
    __syncthreads();

    // ---- Student-t + per-n normalization: warp w handles n = w ---------------
    {
        float d = dsts[w * K_DIM + lane];
        float q = frcp_approx(fmaf(d, d, 1.0f));     // alpha = 1
        float sum = q;
        #pragma unroll
        for (int off = 16; off > 0; off >>= 1)
            sum += __shfl_xor_sync(0xffffffffu, sum, off);
        out[(size_t)(nBase + w) * K_DIM + lane] = q * frcp_approx(sum);
    }
}

extern "C" void kernel_launch(void* const* d_in, const int* in_sizes, int n_in,
                              void* d_out, int out_size) {
    const float* x        = (const float*)d_in[0];   // (2048, 128, 32)
    const float* clusters = (const float*)d_in[1];   // (32, 128, 32)
    float* out            = (float*)d_out;           // (2048, 32)
    (void)in_sizes; (void)n_in; (void)out_size;

    cudaFuncSetAttribute(ts_clustering_kernel,
                         cudaFuncAttributeMaxDynamicSharedMemorySize, SMEM_BYTES);
    ts_clustering_kernel<<<NBLOCKS, THREADS, SMEM_BYTES>>>(x, clusters, out);
}

// round 9
// speedup vs baseline: 3.6110x; 1.3355x over previous
#include <cuda_runtime.h>
#include <cstdint>

// Shapes (fixed)
#define N_TOTAL 2048
#define T_DIM   128
#define F_DIM   32
#define K_DIM   32

#define NB      16                 // n per block
#define TC      8                  // t per chunk
#define CHUNKS  (T_DIM / TC)       // 16
#define THREADS 256                // 8 warps: 2 n-groups x 4 k-groups
#define NBLOCKS (N_TOTAL / NB)     // 128
#define NSLOTS  4

#define XBUF_FLOATS (NB * TC * F_DIM)      // 4096 (16KB/slot)
#define CBUF_FLOATS (K_DIM * TC * F_DIM)   // 8192 (32KB/slot)
#define XBYTES      (XBUF_FLOATS * 4)
#define CBYTES      (CBUF_FLOATS * 4)
#define SMEM_BYTES  (NSLOTS * (XBYTES + CBYTES))   // 192KB

typedef unsigned long long u64;

__device__ __forceinline__ void cp_async16(uint32_t dst, const void* src) {
    asm volatile("cp.async.cg.shared.global [%0], [%1], 16;\n" :: "r"(dst), "l"(src));
}
__device__ __forceinline__ void cp_commit() {
    asm volatile("cp.async.commit_group;\n" ::: "memory");
}
__device__ __forceinline__ void cp_wait2() {
    asm volatile("cp.async.wait_group 2;\n" ::: "memory");
}
__device__ __forceinline__ void ffma2(u64& d, u64 a, u64 b, u64 c) {
    asm("fma.rn.f32x2 %0, %1, %2, %3;" : "=l"(d) : "l"(a), "l"(b), "l"(c));
}
__device__ __forceinline__ u64 fadd2(u64 a, u64 b) {
    u64 d; asm("add.rn.f32x2 %0, %1, %2;" : "=l"(d) : "l"(a), "l"(b)); return d;
}
__device__ __forceinline__ float fsqrt_approx(float v) {
    float r; asm("sqrt.approx.f32 %0, %1;" : "=f"(r) : "f"(v)); return r;
}
__device__ __forceinline__ float frcp_approx(float v) {
    float r; asm("rcp.approx.f32 %0, %1;" : "=f"(r) : "f"(v)); return r;
}
__device__ __forceinline__ u64 lds64(const float* p) {
    return *reinterpret_cast<const u64*>(p);
}
__device__ __forceinline__ float lo32(u64 v) { return __uint_as_float((unsigned)v); }
__device__ __forceinline__ float hi32(u64 v) { return __uint_as_float((unsigned)(v >> 32)); }

#define NEG2_PACKED 0xC0000000C0000000ULL

extern "C" __global__ void __launch_bounds__(THREADS, 1)
ts_clustering_kernel(const float* __restrict__ x,
                     const float* __restrict__ clusters,
                     float* __restrict__ out) {
    extern __shared__ float smem[];
    const uint32_t smem_u32 = (uint32_t)__cvta_generic_to_shared(smem);

    const int tid  = threadIdx.x;
    const int lane = tid & 31;
    const int w    = tid >> 5;          // 0..7
    const int wn   = w & 1;             // n-group: 8 n each
    const int wk   = w >> 1;            // k-group: 8 k each
    const int fp   = lane & 15;         // f-pair 0..15
    const int nsub = lane >> 4;         // n-half
    const int nBase = blockIdx.x * NB;

    const int base_n = wn * 8 + nsub * 4;   // 4 n's per lane
    const int base_k = wk * 8;              // 8 k's per warp

    // ---- persistent prefetch pointers (advance 1KB per chunk) ----------------
    // x chunk: 1024 x 16B -> 4 per thread;  c chunk: 2048 x 16B -> 8 per thread
    const char* xsrc0; const char* xsrc1; const char* xsrc2; const char* xsrc3;
    uint32_t    xdst0, xdst1, xdst2, xdst3;
    {
        int i0 = tid, i1 = tid + 256, i2 = tid + 512, i3 = tid + 768;
        xsrc0 = (const char*)x + ((size_t)(nBase + (i0 >> 6)) * T_DIM) * (F_DIM * 4) + (size_t)(i0 & 63) * 16;
        xsrc1 = (const char*)x + ((size_t)(nBase + (i1 >> 6)) * T_DIM) * (F_DIM * 4) + (size_t)(i1 & 63) * 16;
        xsrc2 = (const char*)x + ((size_t)(nBase + (i2 >> 6)) * T_DIM) * (F_DIM * 4) + (size_t)(i2 & 63) * 16;
        xsrc3 = (const char*)x + ((size_t)(nBase + (i3 >> 6)) * T_DIM) * (F_DIM * 4) + (size_t)(i3 & 63) * 16;
        xdst0 = smem_u32 + (uint32_t)i0 * 16;
        xdst1 = smem_u32 + (uint32_t)i1 * 16;
        xdst2 = smem_u32 + (uint32_t)i2 * 16;
        xdst3 = smem_u32 + (uint32_t)i3 * 16;
    }
    const char* csrc[8];
    uint32_t    cdst[8];
    #pragma unroll
    for (int r = 0; r < 8; r++) {
        int idx = tid + r * 256;
        csrc[r] = (const char*)clusters + ((size_t)(idx >> 6) * T_DIM) * (F_DIM * 4)
                + (size_t)(idx & 63) * 16;
        cdst[r] = smem_u32 + (uint32_t)(NSLOTS * XBYTES) + (uint32_t)idx * 16;
    }
    const int STEP = TC * F_DIM * 4;   // 1KB per chunk advance

    auto prefetch = [&](int slot) {
        const uint32_t xo = (uint32_t)slot * XBYTES;
        const uint32_t co = (uint32_t)slot * CBYTES;
        cp_async16(xdst0 + xo, xsrc0); xsrc0 += STEP;
        cp_async16(xdst1 + xo, xsrc1); xsrc1 += STEP;
        cp_async16(xdst2 + xo, xsrc2); xsrc2 += STEP;
        cp_async16(xdst3 + xo, xsrc3); xsrc3 += STEP;
        #pragma unroll
        for (int r = 0; r < 8; r++) { cp_async16(cdst[r] + co, csrc[r]); csrc[r] += STEP; }
    };

    // ---- accumulators (all static indexing) ----------------------------------
    u64 acc[4][8];
    #pragma unroll
    for (int i = 0; i < 4; i++)
        #pragma unroll
        for (int j = 0; j < 8; j++) acc[i][j] = 0ULL;
    u64 sx2p[4] = {0ULL, 0ULL, 0ULL, 0ULL};                   // (t&3)==wk phase
    u64 sc2p[8] = {0ULL,0ULL,0ULL,0ULL,0ULL,0ULL,0ULL,0ULL};  // (t&1)==wn phase

    prefetch(0); cp_commit();
    prefetch(1); cp_commit();

    #pragma unroll 4
    for (int ci = 0; ci < CHUNKS; ci++) {
        if (ci + 2 < CHUNKS) prefetch((ci + 2) & 3);
        cp_commit();            // uniform group count (empty tail groups)
        cp_wait2();             // chunk ci's group complete (2 newer may be in flight)
        __syncthreads();        // all threads' copies for chunk ci now visible

        const float* xs = smem + (ci & 3) * XBUF_FLOATS;                        // [NB][TC][F]
        const float* cs = smem + NSLOTS * XBUF_FLOATS + (ci & 3) * CBUF_FLOATS; // [K][TC][F]
        const float* xp = xs + (base_n * TC) * F_DIM + 2 * fp;
        const float* cp = cs + (base_k * TC) * F_DIM + 2 * fp;

        #pragma unroll
        for (int t = 0; t < TC; t++) {
            u64 xr[4], cr[8];
            #pragma unroll
            for (int i = 0; i < 4; i++)
                xr[i] = lds64(xp + (i * TC + t) * F_DIM);
            #pragma unroll
            for (int j = 0; j < 8; j++)
                cr[j] = lds64(cp + (j * TC + t) * F_DIM);
            #pragma unroll
            for (int i = 0; i < 4; i++)
                #pragma unroll
                for (int j = 0; j < 8; j++)
                    ffma2(acc[i][j], xr[i], cr[j], acc[i][j]);
            if ((t & 3) == wk) {
                #pragma unroll
                for (int i = 0; i < 4; i++) ffma2(sx2p[i], xr[i], xr[i], sx2p[i]);
            }
            if ((t & 1) == wn) {
                #pragma unroll
                for (int j = 0; j < 8; j++) ffma2(sc2p[j], cr[j], cr[j], sc2p[j]);
            }
        }
        // NOTE: no trailing barrier. The barrier at the top of iteration ci+1
        // guarantees all warps finished chunk ci before prefetch(ci+3) can
        // touch slot (ci+3)&3 == (ci-1)&3, which was last read in iter ci-1.
    }

    // ---- epilogue ------------------------------------------------------------
    __syncthreads();
    float* x2part = smem;            // [4 wk][16 n][16 fp] pairs = 2048 floats
    float* c2part = smem + 2048;     // [2 wn][32 k][16 fp] pairs = 2048 floats
    float* dsts   = smem + 4096;     // [16 n][32 k] = 512 floats

    #pragma unroll
    for (int i = 0; i < 4; i++) {
        int n = base_n + i;
        *reinterpret_cast<u64*>(&x2part[2 * ((wk * 16 + n) * 16 + fp)]) = sx2p[i];
    }
    if (nsub == 0) {                 // both halves hold identical sc2p
        #pragma unroll
        for (int j = 0; j < 8; j++) {
            int k = base_k + j;
            *reinterpret_cast<u64*>(&c2part[2 * ((wn * 32 + k) * 16 + fp)]) = sc2p[j];
        }
    }
    __syncthreads();

    u64 c2p[8];
    #pragma unroll
    for (int j = 0; j < 8; j++) {
        int k = base_k + j;
        c2p[j] = fadd2(lds64(&c2part[2 * ((0 * 32 + k) * 16 + fp)]),
                       lds64(&c2part[2 * ((1 * 32 + k) * 16 + fp)]));
    }

    #pragma unroll
    for (int i = 0; i < 4; i++) {
        int n = base_n + i;
        u64 x2p = fadd2(fadd2(lds64(&x2part[2 * ((0 * 16 + n) * 16 + fp)]),
                              lds64(&x2part[2 * ((1 * 16 + n) * 16 + fp)])),
                        fadd2(lds64(&x2part[2 * ((2 * 16 + n) * 16 + fp)]),
                              lds64(&x2part[2 * ((3 * 16 + n) * 16 + fp)])));
        #pragma unroll
        for (int j = 0; j < 8; j++) {
            u64 s  = fadd2(x2p, c2p[j]);
            u64 sq;
            ffma2(sq, acc[i][j], NEG2_PACKED, s);   // x2 + c2 - 2*xc (both f's)
            float ed = fsqrt_approx(fmaxf(lo32(sq), 0.0f))
                     + fsqrt_approx(fmaxf(hi32(sq), 0.0f));
            #pragma unroll
            for (int off = 8; off > 0; off >>= 1)   // reduce 16 f-pairs per half
                ed += __shfl_xor_sync(0xffffffffu, ed, off);
            if (fp == 0)                             // lanes 0 & 16: distinct n
                dsts[n * K_DIM + (base_k + j)] = ed;
        }
    }
    __syncthreads();

    // ---- Student-t + per-n normalization: warp w handles n = w, w+8 ----------
    #pragma unroll
    for (int n = w; n < NB; n += 8) {
        float d = dsts[n * K_DIM + lane];
        float q = frcp_approx(fmaf(d, d, 1.0f));     // alpha = 1
        float sum = q;
        #pragma unroll
        for (int off = 16; off > 0; off >>= 1)
            sum += __shfl_xor_sync(0xffffffffu, sum, off);
        out[(size_t)(nBase + n) * K_DIM + lane] = q * frcp_approx(sum);
    }
}

extern "C" void kernel_launch(void* const* d_in, const int* in_sizes, int n_in,
                              void* d_out, int out_size) {
    const float* x        = (const float*)d_in[0];   // (2048, 128, 32)
    const float* clusters = (const float*)d_in[1];   // (32, 128, 32)
    float* out            = (float*)d_out;           // (2048, 32)
    (void)in_sizes; (void)n_in; (void)out_size;

    cudaFuncSetAttribute(ts_clustering_kernel,
                         cudaFuncAttributeMaxDynamicSharedMemorySize, SMEM_BYTES);
    ts_clustering_kernel<<<NBLOCKS, THREADS, SMEM_BYTES>>>(x, clusters, out);
}